// round 3
// baseline (speedup 1.0000x reference)
#include <cuda_runtime.h>

// Problem constants
#define BSZ   32
#define NSZ   256
#define KSZ   16
#define INC   32
#define OUTC  32

// Scratch (allocation-free: __device__ globals)
__device__ float g_S[BSZ * 32 * 32];              // [s][B][i]
__device__ float g_Tpart[8 * 2 * BSZ * KSZ * OUTC]; // [ich][par][s][k][o]
__device__ float g_wdT[KSZ * OUTC * INC];          // [k][o][i]

// ---------------------------------------------------------------------------
// Kernel 1: pooled/gathered S[s][B][i] = sum_r x[s, perm[8B+r], i]
//           + transpose w_diag -> g_wdT[k][o][i]
// grid 128 x 256 threads = 32768 threads (one per S element)
// ---------------------------------------------------------------------------
__global__ void __launch_bounds__(256) prep_kernel(
    const float* __restrict__ x,
    const float* __restrict__ w_diag,
    const int*   __restrict__ perm)
{
    int idx = blockIdx.x * 256 + threadIdx.x;   // 0..32767
    int s = idx >> 10;
    int B = (idx >> 5) & 31;
    int i = idx & 31;
    const float* xs = x + s * (NSZ * INC) + i;
    float acc = 0.f;
#pragma unroll
    for (int r = 0; r < 8; r++) {
        int n = __ldg(&perm[B * 8 + r]);
        acc += __ldg(&xs[n * INC]);
    }
    g_S[idx] = acc;

    if (idx < KSZ * OUTC * INC) {
        // idx = c*16 + k  (coalesced read of w_diag)
        int c = idx >> 4;
        int k = idx & 15;
        g_wdT[k * 1024 + c] = w_diag[idx];   // g_wdT[k][o][i], c = o*32+i
    }
}

// ---------------------------------------------------------------------------
// Kernel 2: T[p][s][k][o] partials.
// Block = (k, i-chunk of 4): 16*8 = 128 blocks, 256 threads.
// Thread t -> s = t>>3, og = t&7, handles o in {og, og+8, og+16, og+24},
// both parities, contraction over (ic in 4) x (B in 32) via float4 dots.
// Shared layouts use stride-33 float4 rows: all LDS.128 conflict-free.
// ---------------------------------------------------------------------------
__global__ void __launch_bounds__(256) main_gemm(const float* __restrict__ w_off)
{
    int k  = blockIdx.x >> 3;
    int ich = blockIdx.x & 7;
    int i0 = ich * 4;
    int t = threadIdx.x;

    __shared__ float Wsh[32 * 33 * 4];   // [o][B] float4 rows, stride 33
    __shared__ float Ssh[32 * 33 * 4];   // [s][B] float4 rows, stride 33

    // Load W tile: w_off[(o*32 + i0+ic)*512 + k*32 + B], 4096 elems
#pragma unroll
    for (int j = 0; j < 16; j++) {
        int e  = j * 256 + t;            // e = o*128 + ic*32 + B (B fastest: coalesced)
        int o  = e >> 7;
        int ic = (e >> 5) & 3;
        int B  = e & 31;
        Wsh[(o * 33 + B) * 4 + ic] = w_off[(o * 32 + i0 + ic) * 512 + k * 32 + B];
    }
    // Load S tile: g_S[s*1024 + B*32 + i0+ic], 4096 elems
#pragma unroll
    for (int j = 0; j < 16; j++) {
        int e  = j * 256 + t;            // e = s*128 + B*4 + ic
        int s  = e >> 7;
        int B  = (e >> 2) & 31;
        int ic = e & 3;
        Ssh[(s * 33 + B) * 4 + ic] = g_S[s * 1024 + B * 32 + i0 + ic];
    }
    __syncthreads();

    int s  = t >> 3;
    int og = t & 7;
    const float4* Sv = (const float4*)Ssh;
    const float4* Wv = (const float4*)Wsh;

    float accU[4] = {0.f, 0.f, 0.f, 0.f};
    float accV[4] = {0.f, 0.f, 0.f, 0.f};

#pragma unroll 8
    for (int B = 0; B < 32; B++) {
        float4 sU = Sv[s * 33 + B];
        float4 sV = Sv[s * 33 + (B ^ 1)];
#pragma unroll
        for (int oo = 0; oo < 4; oo++) {
            float4 w = Wv[(og + 8 * oo) * 33 + B];
            accU[oo] += w.x * sU.x + w.y * sU.y + w.z * sU.z + w.w * sU.w;
            accV[oo] += w.x * sV.x + w.y * sV.y + w.z * sV.z + w.w * sV.w;
        }
    }

#pragma unroll
    for (int oo = 0; oo < 4; oo++) {
        int o = og + 8 * oo;
        g_Tpart[(((ich * 2 + 0) * 32 + s) * 16 + k) * 32 + o] = accU[oo];
        g_Tpart[(((ich * 2 + 1) * 32 + s) * 16 + k) * 32 + o] = accV[oo];
    }
}

// ---------------------------------------------------------------------------
// Kernel 3: finalize. Block = (s, k): 32*16 = 512 blocks, 512 threads,
// thread = (a_loc in 16, o in 32).
//   out[s, perm[16k+a_loc], o] = T/256 + sum_i xp[s,a,i]*w_diag[(o,i),k] + b1[o]
// ---------------------------------------------------------------------------
__global__ void __launch_bounds__(512) final_kernel(
    const float* __restrict__ x,
    const float* __restrict__ b1,
    const int*   __restrict__ perm,
    float*       __restrict__ out)
{
    int s = blockIdx.x >> 4;
    int k = blockIdx.x & 15;
    int t = threadIdx.x;

    __shared__ float wdsh[32 * 33];   // [o][i], pad 33 (conflict-free scalar LDS)
    __shared__ float xpsh[16 * 32];   // [a_loc][i]
    __shared__ float tsh[64];         // [par][o]
    __shared__ float bsh[32];

    int a_loc = t >> 5;
    int lane  = t & 31;
    int n = __ldg(&perm[k * 16 + a_loc]);

    // xp gather (coalesced rows)
    xpsh[t] = x[s * (NSZ * INC) + n * 32 + lane];

    // w_diag slice for this k (coalesced from transposed copy)
    {
        int e = t;
#pragma unroll
        for (int j = 0; j < 2; j++) {
            int o = e >> 5, i = e & 31;
            wdsh[o * 33 + i] = g_wdT[k * 1024 + e];
            e += 512;
        }
    }
    if (t < 32) bsh[t] = b1[t];
    if (t < 64) {
        int par = t >> 5, o = t & 31;
        float acc = 0.f;
#pragma unroll
        for (int ich = 0; ich < 8; ich++)
            acc += g_Tpart[(((ich * 2 + par) * 32 + s) * 16 + k) * 32 + o];
        tsh[t] = acc * (1.f / 256.f);
    }
    __syncthreads();

    int o = lane;
    float acc = tsh[(a_loc >> 3) * 32 + o] + bsh[o];
#pragma unroll
    for (int ii = 0; ii < 32; ii++)
        acc += xpsh[a_loc * 32 + ii] * wdsh[o * 33 + ii];

    // scatter: out[s, perm[a], o]
    out[s * (NSZ * OUTC) + n * 32 + o] = acc;
}

// ---------------------------------------------------------------------------
extern "C" void kernel_launch(void* const* d_in, const int* in_sizes, int n_in,
                              void* d_out, int out_size)
{
    const float* x      = (const float*)d_in[0];
    const float* w_diag = (const float*)d_in[1];
    const float* w_off  = (const float*)d_in[2];
    const float* b1     = (const float*)d_in[3];
    const int*   perm   = (const int*)d_in[4];
    // d_in[5] (inv_permute) not needed: we scatter through perm directly.
    float* out = (float*)d_out;

    prep_kernel<<<128, 256>>>(x, w_diag, perm);
    main_gemm<<<128, 256>>>(w_off);
    final_kernel<<<512, 512>>>(x, b1, perm, out);
}